// round 1
// baseline (speedup 1.0000x reference)
#include <cuda_runtime.h>

// DSSIM_46849503265169 — fused separable-Gaussian SSIM + mean
// Inputs: d_in[0]=image1 [32,3,512,512] f32, d_in[1]=image2, d_in[2]=gauss_kernel [3,1,11,11] f32
// Output: d_out[0] = mean((1 - ssim_map)/2)

#define IMH 512
#define IMW 512
#define NPLANE 96            // 32*3
#define TW 32
#define TH 32
#define HALO 5
#define INW 42               // TW + 2*HALO
#define INH 42
#define INP 43               // sIn pitch (float2 units) — odd to kill row-phase bank conflicts
#define HBP 33               // hb pitch
#define NBLK (16*16*96)      // 24576
#define C1F 0.0001f
#define C2F 0.0009f

typedef unsigned long long u64;

__device__ __forceinline__ u64 pk2(float lo, float hi) {
    u64 r; asm("mov.b64 %0, {%1,%2};" : "=l"(r) : "f"(lo), "f"(hi)); return r;
}
__device__ __forceinline__ void up2(u64 v, float& lo, float& hi) {
    asm("mov.b64 {%0,%1}, %2;" : "=f"(lo), "=f"(hi) : "l"(v));
}
__device__ __forceinline__ u64 fma2(u64 a, u64 b, u64 c) {
    u64 d; asm("fma.rn.f32x2 %0, %1, %2, %3;" : "=l"(d) : "l"(a), "l"(b), "l"(c)); return d;
}
__device__ __forceinline__ u64 mul2(u64 a, u64 b) {
    u64 d; asm("mul.rn.f32x2 %0, %1, %2;" : "=l"(d) : "l"(a), "l"(b)); return d;
}

__device__ double g_part[NBLK];

__global__ __launch_bounds__(256) void dssim_main(
    const float* __restrict__ im1,
    const float* __restrict__ im2,
    const float* __restrict__ kern)
{
    __shared__ float2 sIn[INH * INP];   // (im1, im2) interleaved, with halo
    __shared__ float2 sMu[INH * HBP];   // horizontal blur of (im1, im2)
    __shared__ float2 sSq[INH * HBP];   // horizontal blur of (im1^2, im2^2)
    __shared__ float  sXy[INH * HBP];   // horizontal blur of im1*im2
    __shared__ float  sW[11];
    __shared__ float  sWarp[8];

    const int tid = threadIdx.x;
    const int x0 = blockIdx.x * TW;
    const int y0 = blockIdx.y * TH;
    const size_t pbase = (size_t)blockIdx.z * (IMH * IMW);

    // 1D weights: row-sums of the normalized 2D kernel (K = outer(w,w), sum(K)=1)
    if (tid < 11) {
        float s = 0.f;
        #pragma unroll
        for (int j = 0; j < 11; ++j) s += kern[tid * 11 + j];
        sW[tid] = s;
    }

    // Load tile + halo, zero-padded (matches conv SAME zero padding)
    for (int i = tid; i < INH * INW; i += 256) {
        int r = i / INW;
        int c = i - r * INW;
        int gy = y0 + r - HALO;
        int gx = x0 + c - HALO;
        float v1 = 0.f, v2 = 0.f;
        if ((unsigned)gy < IMH && (unsigned)gx < IMW) {
            size_t off = pbase + (size_t)gy * IMW + gx;
            v1 = im1[off];
            v2 = im2[off];
        }
        sIn[r * INP + c] = make_float2(v1, v2);
    }
    __syncthreads();

    float w[11]; u64 ww[11];
    #pragma unroll
    for (int t = 0; t < 11; ++t) { w[t] = sW[t]; ww[t] = pk2(w[t], w[t]); }

    // ---- Horizontal pass: streaming 4-output groups, f32x2-packed fields ----
    for (int g = tid; g < INH * (TW / 4); g += 256) {
        int r  = g >> 3;
        int cx = (g & 7) << 2;
        u64 aMu[4], aSq[4]; float aXy[4];
        #pragma unroll
        for (int j = 0; j < 4; ++j) { aMu[j] = 0ull; aSq[j] = 0ull; aXy[j] = 0.f; }
        const float2* rowp = &sIn[r * INP + cx];
        #pragma unroll
        for (int k = 0; k < 14; ++k) {
            float2 v = rowp[k];
            u64 A = pk2(v.x, v.y);
            u64 P = mul2(A, A);
            float pxy = v.x * v.y;
            #pragma unroll
            for (int j = 0; j < 4; ++j) {
                int t = k - j;
                if (t >= 0 && t <= 10) {
                    aMu[j] = fma2(ww[t], A, aMu[j]);
                    aSq[j] = fma2(ww[t], P, aSq[j]);
                    aXy[j] = fmaf(w[t], pxy, aXy[j]);
                }
            }
        }
        #pragma unroll
        for (int j = 0; j < 4; ++j) {
            float lo, hi;
            up2(aMu[j], lo, hi); sMu[r * HBP + cx + j] = make_float2(lo, hi);
            up2(aSq[j], lo, hi); sSq[r * HBP + cx + j] = make_float2(lo, hi);
            sXy[r * HBP + cx + j] = aXy[j];
        }
    }
    __syncthreads();

    // ---- Vertical pass + pointwise SSIM + partial sum ----
    const int x  = tid & 31;
    const int ys = (tid >> 5) * 4;     // 8 warps * 4 rows = 32 rows
    u64 aMu[4], aSq[4]; float aXy[4];
    #pragma unroll
    for (int j = 0; j < 4; ++j) { aMu[j] = 0ull; aSq[j] = 0ull; aXy[j] = 0.f; }
    #pragma unroll
    for (int k = 0; k < 14; ++k) {
        float2 m  = sMu[(ys + k) * HBP + x];
        float2 sq = sSq[(ys + k) * HBP + x];
        float  xy = sXy[(ys + k) * HBP + x];
        u64 M = pk2(m.x, m.y);
        u64 S = pk2(sq.x, sq.y);
        #pragma unroll
        for (int j = 0; j < 4; ++j) {
            int t = k - j;
            if (t >= 0 && t <= 10) {
                aMu[j] = fma2(ww[t], M, aMu[j]);
                aSq[j] = fma2(ww[t], S, aSq[j]);
                aXy[j] = fmaf(w[t], xy, aXy[j]);
            }
        }
    }

    float local = 0.f;
    #pragma unroll
    for (int j = 0; j < 4; ++j) {
        float mu1, mu2, bxx, byy;
        up2(aMu[j], mu1, mu2);
        up2(aSq[j], bxx, byy);
        float bxy  = aXy[j];
        float mu11 = mu1 * mu1, mu22 = mu2 * mu2, mu12 = mu1 * mu2;
        float s1  = bxx - mu11;
        float s2  = byy - mu22;
        float s12 = bxy - mu12;
        float num = fmaf(2.f, mu12, C1F) * fmaf(2.f, s12, C2F);
        float den = (mu11 + mu22 + C1F) * (s1 + s2 + C2F);
        local += (1.f - __fdividef(num, den)) * 0.5f;
    }

    // Deterministic in-block reduction (fixed shuffle tree)
    #pragma unroll
    for (int o = 16; o; o >>= 1) local += __shfl_xor_sync(0xffffffffu, local, o);
    if ((tid & 31) == 0) sWarp[tid >> 5] = local;
    __syncthreads();
    if (tid == 0) {
        float bs = 0.f;
        #pragma unroll
        for (int i = 0; i < 8; ++i) bs += sWarp[i];
        g_part[((int)blockIdx.z * 16 + (int)blockIdx.y) * 16 + (int)blockIdx.x] = (double)bs;
    }
}

__global__ __launch_bounds__(256) void dssim_reduce(float* __restrict__ out)
{
    __shared__ double sd[256];
    int t = threadIdx.x;
    double s = 0.0;
    for (int i = t; i < NBLK; i += 256) s += g_part[i];   // fixed order: deterministic
    sd[t] = s;
    __syncthreads();
    #pragma unroll
    for (int o = 128; o; o >>= 1) {
        if (t < o) sd[t] += sd[t + o];
        __syncthreads();
    }
    if (t == 0) out[0] = (float)(sd[0] / (double)(32.0 * 3.0 * 512.0 * 512.0));
}

extern "C" void kernel_launch(void* const* d_in, const int* in_sizes, int n_in,
                              void* d_out, int out_size)
{
    const float* im1  = (const float*)d_in[0];
    const float* im2  = (const float*)d_in[1];
    const float* kern = (const float*)d_in[2];
    float* out = (float*)d_out;

    dim3 grid(IMW / TW, IMH / TH, NPLANE);   // 16 x 16 x 96
    dssim_main<<<grid, 256>>>(im1, im2, kern);
    dssim_reduce<<<1, 256>>>(out);
}